// round 1
// baseline (speedup 1.0000x reference)
#include <cuda_runtime.h>
#include <math.h>

#define Bn   16
#define Ss   512
#define Dd   512
#define Hh   8
#define HSs  2
#define DKk  64
#define DFFf 2048
#define NGATE 6   // H - HS

// ---------------- scratch (device globals; no allocation allowed) ----------------
__device__ float g_y[Bn*Ss*Dd];
__device__ float g_x[Bn*Ss*Dd];
__device__ float g_qlin[Bn*Ss*Dd];
__device__ float g_v[Bn*Ss*Dd];
__device__ float g_scores[Bn*Hh*Ss*Ss];     // 33.5M floats = 134 MB
__device__ float g_ctx[Bn*Ss*Dd];
__device__ float g_tmp[Bn*Ss*Dd];
__device__ float g_ffn[Bn*Ss*DFFf];
__device__ float g_dyn[Bn*Ss*NGATE];
__device__ float g_rmask[Bn*Hh];

// ---------------- generic batched GEMM ----------------
// C[z] = epilogue( alpha * A[z] @ (B[z] or B[z]^T) )   with per-z offsets split
// into (batch, head) components:  off = (z/nH)*s?b + (z%nH)*s?h
// epilogue: *scaleZ[z] (if given), + bias[n] (if given), relu (if flag)
template<bool TRANSB>
__global__ void __launch_bounds__(256) gemm_kernel(
    const float* __restrict__ A, const float* __restrict__ Bm,
    const float* __restrict__ bias, float* __restrict__ C,
    int M, int N, int K, int lda, int ldb, int ldc,
    long long sAb, long long sAh, long long sBb, long long sBh,
    long long sCb, long long sCh, int nH,
    float alpha, const float* __restrict__ scaleZ, int relu)
{
    int z = blockIdx.z;
    int zb = z / nH, zh = z % nH;
    A  += zb * sAb + (long long)zh * sAh;
    Bm += zb * sBb + (long long)zh * sBh;
    C  += zb * sCb + (long long)zh * sCh;

    __shared__ __align__(16) float As[16][68];   // row stride 272B -> 16B aligned
    __shared__ __align__(16) float Bs[16][68];

    int tid = threadIdx.x;
    int tx = tid & 15, ty = tid >> 4;
    int row0 = blockIdx.y * 64;
    int col0 = blockIdx.x * 64;

    float acc[4][4];
    #pragma unroll
    for (int i = 0; i < 4; i++)
        #pragma unroll
        for (int j = 0; j < 4; j++) acc[i][j] = 0.f;

    for (int k0 = 0; k0 < K; k0 += 16) {
        // load A tile (64 rows x 16 k)  -> As[k][m]
        #pragma unroll
        for (int l = 0; l < 4; l++) {
            int idx = tid + l * 256;
            int m = idx >> 4, k = idx & 15;
            As[k][m] = A[(long long)(row0 + m) * lda + (k0 + k)];
        }
        // load B tile -> Bs[k][n]
        #pragma unroll
        for (int l = 0; l < 4; l++) {
            int idx = tid + l * 256;
            if (TRANSB) {
                int n = idx >> 4, k = idx & 15;
                Bs[k][n] = Bm[(long long)(col0 + n) * ldb + (k0 + k)];
            } else {
                int k = idx >> 6, n = idx & 63;
                Bs[k][n] = Bm[(long long)(k0 + k) * ldb + (col0 + n)];
            }
        }
        __syncthreads();
        #pragma unroll
        for (int k = 0; k < 16; k++) {
            float4 a = *(const float4*)&As[k][ty * 4];
            float4 b = *(const float4*)&Bs[k][tx * 4];
            acc[0][0] += a.x*b.x; acc[0][1] += a.x*b.y; acc[0][2] += a.x*b.z; acc[0][3] += a.x*b.w;
            acc[1][0] += a.y*b.x; acc[1][1] += a.y*b.y; acc[1][2] += a.y*b.z; acc[1][3] += a.y*b.w;
            acc[2][0] += a.z*b.x; acc[2][1] += a.z*b.y; acc[2][2] += a.z*b.z; acc[2][3] += a.z*b.w;
            acc[3][0] += a.w*b.x; acc[3][1] += a.w*b.y; acc[3][2] += a.w*b.z; acc[3][3] += a.w*b.w;
        }
        __syncthreads();
    }

    float sc = alpha;
    if (scaleZ) sc *= scaleZ[z];
    #pragma unroll
    for (int i = 0; i < 4; i++) {
        int m = row0 + ty * 4 + i;
        int n0 = col0 + tx * 4;
        float4 o;
        float v0 = acc[i][0] * sc, v1 = acc[i][1] * sc, v2 = acc[i][2] * sc, v3 = acc[i][3] * sc;
        if (bias) { v0 += bias[n0]; v1 += bias[n0+1]; v2 += bias[n0+2]; v3 += bias[n0+3]; }
        if (relu) { v0 = fmaxf(v0,0.f); v1 = fmaxf(v1,0.f); v2 = fmaxf(v2,0.f); v3 = fmaxf(v3,0.f); }
        o.x = v0; o.y = v1; o.z = v2; o.w = v3;
        *(float4*)&C[(long long)m * ldc + n0] = o;
    }
}

// ---------------- mask + softmax over score rows ----------------
// row layout: blockIdx.x = (b*H + h)*S + i ; 128 threads
__global__ void softmax_kernel(float* __restrict__ scores, int mask_flag)
{
    long long row = blockIdx.x;
    int i = (int)(row % Ss);
    float* p = scores + row * Ss;
    int tid = threadIdx.x;

    if (i == 0) {   // pad_zero: entire row forced to 0 before softmax -> uniform
        const float u = 1.0f / Ss;
        for (int j = tid; j < Ss; j += 128) p[j] = u;
        return;
    }
    int limit = mask_flag ? (i + 1) : i;   // allowed keys j < limit

    __shared__ float red[4];
    float m = -1e30f;
    for (int j = tid; j < limit; j += 128) m = fmaxf(m, p[j]);
    #pragma unroll
    for (int o = 16; o; o >>= 1) m = fmaxf(m, __shfl_xor_sync(0xffffffffu, m, o));
    if ((tid & 31) == 0) red[tid >> 5] = m;
    __syncthreads();
    m = fmaxf(fmaxf(red[0], red[1]), fmaxf(red[2], red[3]));
    __syncthreads();

    float s = 0.f;
    for (int j = tid; j < limit; j += 128) {
        float e = expf(p[j] - m);
        p[j] = e;
        s += e;
    }
    #pragma unroll
    for (int o = 16; o; o >>= 1) s += __shfl_xor_sync(0xffffffffu, s, o);
    if ((tid & 31) == 0) red[tid >> 5] = s;
    __syncthreads();
    s = red[0] + red[1] + red[2] + red[3];
    float inv = 1.0f / s;
    for (int j = tid; j < limit; j += 128) p[j] *= inv;
    for (int j = limit + tid; j < Ss; j += 128) p[j] = 0.f;   // exp(-1e9-m) == 0 in fp32
}

// ---------------- residual + LayerNorm ----------------
// blockIdx.x = row over B*S ; 256 threads, 2 elements each (D=512)
__global__ void add_ln_kernel(const float* __restrict__ resid, const float* __restrict__ delta,
                              const float* __restrict__ g, const float* __restrict__ b,
                              float* __restrict__ out)
{
    long long base = (long long)blockIdx.x * Dd;
    int tid = threadIdx.x;
    float v0 = resid[base + tid]       + delta[base + tid];
    float v1 = resid[base + tid + 256] + delta[base + tid + 256];
    float s  = v0 + v1;
    float sq = v0 * v0 + v1 * v1;

    __shared__ float rs[8], rq[8];
    #pragma unroll
    for (int o = 16; o; o >>= 1) {
        s  += __shfl_xor_sync(0xffffffffu, s,  o);
        sq += __shfl_xor_sync(0xffffffffu, sq, o);
    }
    if ((tid & 31) == 0) { rs[tid >> 5] = s; rq[tid >> 5] = sq; }
    __syncthreads();
    s = 0.f; sq = 0.f;
    #pragma unroll
    for (int w2 = 0; w2 < 8; w2++) { s += rs[w2]; sq += rq[w2]; }

    float mu   = s * (1.0f / Dd);
    float var  = sq * (1.0f / Dd) - mu * mu;
    float rstd = rsqrtf(var + 1e-5f);
    out[base + tid]       = g[tid]       * ((v0 - mu) * rstd) + b[tid];
    out[base + tid + 256] = g[tid + 256] * ((v1 - mu) * rstd) + b[tid + 256];
}

// ---------------- head-routing gate: one warp per token ----------------
__global__ void gating_kernel(const float* __restrict__ qlin, const float* __restrict__ wg,
                              float* __restrict__ dyn)
{
    int gw   = (int)((blockIdx.x * blockDim.x + threadIdx.x) >> 5);
    int lane = threadIdx.x & 31;
    if (gw >= Bn * Ss) return;
    const float* q = qlin + (long long)gw * Dd;

    float acc[NGATE];
    #pragma unroll
    for (int g2 = 0; g2 < NGATE; g2++) acc[g2] = 0.f;
    for (int d = lane; d < Dd; d += 32) {
        float qv = q[d];
        const float* w = wg + d * NGATE;
        #pragma unroll
        for (int g2 = 0; g2 < NGATE; g2++) acc[g2] += qv * w[g2];
    }
    #pragma unroll
    for (int g2 = 0; g2 < NGATE; g2++)
        #pragma unroll
        for (int o = 16; o; o >>= 1) acc[g2] += __shfl_xor_sync(0xffffffffu, acc[g2], o);

    if (lane == 0) {
        int i1 = 0;
        #pragma unroll
        for (int g2 = 1; g2 < NGATE; g2++) if (acc[g2] > acc[i1]) i1 = g2;
        int i2 = (i1 == 0) ? 1 : 0;
        #pragma unroll
        for (int g2 = 0; g2 < NGATE; g2++)
            if (g2 != i1 && acc[g2] > acc[i2]) i2 = g2;

        float mx = acc[i1], sum = 0.f, e[NGATE];
        #pragma unroll
        for (int g2 = 0; g2 < NGATE; g2++) { e[g2] = expf(acc[g2] - mx); sum += e[g2]; }
        float inv = 1.0f / sum;
        #pragma unroll
        for (int g2 = 0; g2 < NGATE; g2++)
            dyn[(long long)gw * NGATE + g2] = (g2 == i1 || g2 == i2) ? e[g2] * inv : 0.f;
    }
}

// ---------------- rmask[b,h] = (h<HS) ? 1 : mean_s dyn[b,s,h-HS] ----------------
__global__ void rmask_kernel(const float* __restrict__ dyn, float* __restrict__ rmask)
{
    int z = blockIdx.x;             // B*H
    int b = z / Hh, h = z % Hh;
    int tid = threadIdx.x;          // 256
    if (h < HSs) { if (tid == 0) rmask[z] = 1.f; return; }
    int g = h - HSs;
    float v = dyn[((long long)(b * Ss + tid))       * NGATE + g]
            + dyn[((long long)(b * Ss + tid + 256)) * NGATE + g];
    __shared__ float rs[8];
    #pragma unroll
    for (int o = 16; o; o >>= 1) v += __shfl_xor_sync(0xffffffffu, v, o);
    if ((tid & 31) == 0) rs[tid >> 5] = v;
    __syncthreads();
    if (tid == 0) {
        float t = 0.f;
        #pragma unroll
        for (int w2 = 0; w2 < 8; w2++) t += rs[w2];
        rmask[z] = t * (1.0f / Ss);
    }
}

// ---------------- host orchestration ----------------
struct Wts {
    const float *wq, *bq, *wv, *bv, *wo, *bo, *wg;
    const float *ln1g, *ln1b, *fw1, *fb1, *fw2, *fb2, *ln2g, *ln2b;
};
struct Scr {
    float *qlin, *v, *scores, *ctx, *tmp, *ffn, *dyn, *rmask;
};

static void gemm(const float* A, const float* Bm, const float* bias, float* C,
                 int M, int N, int K, int lda, int ldb, int ldc,
                 long long sAb, long long sAh, long long sBb, long long sBh,
                 long long sCb, long long sCh, int nH, int batch,
                 float alpha, const float* scaleZ, bool transB, int relu)
{
    dim3 grid(N / 64, M / 64, batch), blk(256);
    if (transB)
        gemm_kernel<true><<<grid, blk>>>(A, Bm, bias, C, M, N, K, lda, ldb, ldc,
                                         sAb, sAh, sBb, sBh, sCb, sCh, nH, alpha, scaleZ, relu);
    else
        gemm_kernel<false><<<grid, blk>>>(A, Bm, bias, C, M, N, K, lda, ldb, ldc,
                                          sAb, sAh, sBb, sBh, sCb, sCh, nH, alpha, scaleZ, relu);
}

static void run_block(float* xq, float* xv, int layer, bool mask_flag, bool apply_pos,
                      const Wts& w, const Scr& s, float* finalOut)
{
    const int M = Bn * Ss;
    const long long DD = (long long)Dd * Dd;

    // qlin = xq @ wq[l] + bq[l]
    gemm(xq, w.wq + layer * DD, w.bq + layer * Dd, s.qlin,
         M, Dd, Dd, Dd, Dd, Dd, 0,0,0,0,0,0, 1, 1, 1.f, nullptr, false, 0);
    // v = xv @ wv[l] + bv[l]
    gemm(xv, w.wv + layer * DD, w.bv + layer * Dd, s.v,
         M, Dd, Dd, Dd, Dd, Dd, 0,0,0,0,0,0, 1, 1, 1.f, nullptr, false, 0);

    // head routing
    gating_kernel<<<(Bn * Ss * 32 + 255) / 256, 256>>>(s.qlin, w.wg + (long long)layer * Dd * NGATE, s.dyn);
    rmask_kernel<<<Bn * Hh, 256>>>(s.dyn, s.rmask);

    // scores[z] = (Qh @ Qh^T) / 8     z = b*H + h
    gemm(s.qlin, s.qlin, nullptr, s.scores,
         Ss, Ss, DKk, Dd, Dd, Ss,
         (long long)Ss * Dd, 64, (long long)Ss * Dd, 64,
         (long long)Hh * Ss * Ss, (long long)Ss * Ss,
         Hh, Bn * Hh, 0.125f, nullptr, true, 0);

    softmax_kernel<<<Bn * Hh * Ss, 128>>>(s.scores, mask_flag ? 1 : 0);

    // ctx = (attn @ Vh) * rmask[z]   written directly into (B,S,D) layout
    gemm(s.scores, s.v, nullptr, s.ctx,
         Ss, DKk, Ss, Ss, Dd, Dd,
         (long long)Hh * Ss * Ss, (long long)Ss * Ss,
         (long long)Ss * Dd, 64, (long long)Ss * Dd, 64,
         Hh, Bn * Hh, 1.f, s.rmask, false, 0);

    // tmp = ctx @ wo[l] + bo[l]
    gemm(s.ctx, w.wo + layer * DD, w.bo + layer * Dd, s.tmp,
         M, Dd, Dd, Dd, Dd, Dd, 0,0,0,0,0,0, 1, 1, 1.f, nullptr, false, 0);

    // x = LN(xq + tmp)   (in place on xq)
    add_ln_kernel<<<M, 256>>>(xq, s.tmp, w.ln1g + layer * Dd, w.ln1b + layer * Dd, xq);

    if (apply_pos) {
        gemm(xq, w.fw1 + (long long)layer * Dd * DFFf, w.fb1 + layer * DFFf, s.ffn,
             M, DFFf, Dd, Dd, DFFf, DFFf, 0,0,0,0,0,0, 1, 1, 1.f, nullptr, false, 1);
        gemm(s.ffn, w.fw2 + (long long)layer * DFFf * Dd, w.fb2 + layer * Dd, s.tmp,
             M, Dd, DFFf, DFFf, Dd, Dd, 0,0,0,0,0,0, 1, 1, 1.f, nullptr, false, 0);
        float* out2 = finalOut ? finalOut : xq;
        add_ln_kernel<<<M, 256>>>(xq, s.tmp, w.ln2g + layer * Dd, w.ln2b + layer * Dd, out2);
    }
}

extern "C" void kernel_launch(void* const* d_in, const int* in_sizes, int n_in,
                              void* d_out, int out_size)
{
    const float* question    = (const float*)d_in[0];
    const float* interaction = (const float*)d_in[1];
    Wts w;
    w.wq   = (const float*)d_in[2];  w.bq   = (const float*)d_in[3];
    w.wv   = (const float*)d_in[4];  w.bv   = (const float*)d_in[5];
    w.wo   = (const float*)d_in[6];  w.bo   = (const float*)d_in[7];
    w.wg   = (const float*)d_in[8];
    w.ln1g = (const float*)d_in[9];  w.ln1b = (const float*)d_in[10];
    w.fw1  = (const float*)d_in[11]; w.fb1  = (const float*)d_in[12];
    w.fw2  = (const float*)d_in[13]; w.fb2  = (const float*)d_in[14];
    w.ln2g = (const float*)d_in[15]; w.ln2b = (const float*)d_in[16];

    float *gx, *gy;
    Scr s;
    cudaGetSymbolAddress((void**)&gx,       g_x);
    cudaGetSymbolAddress((void**)&gy,       g_y);
    cudaGetSymbolAddress((void**)&s.qlin,   g_qlin);
    cudaGetSymbolAddress((void**)&s.v,      g_v);
    cudaGetSymbolAddress((void**)&s.scores, g_scores);
    cudaGetSymbolAddress((void**)&s.ctx,    g_ctx);
    cudaGetSymbolAddress((void**)&s.tmp,    g_tmp);
    cudaGetSymbolAddress((void**)&s.ffn,    g_ffn);
    cudaGetSymbolAddress((void**)&s.dyn,    g_dyn);
    cudaGetSymbolAddress((void**)&s.rmask,  g_rmask);

    size_t bytes = (size_t)Bn * Ss * Dd * sizeof(float);
    cudaMemcpyAsync(gy, interaction, bytes, cudaMemcpyDeviceToDevice);
    cudaMemcpyAsync(gx, question,    bytes, cudaMemcpyDeviceToDevice);

    // knowledge encoder: 2 self-attn blocks on y (mask j<=i, no FFN)
    run_block(gy, gy, 0, true,  false, w, s, nullptr);
    run_block(gy, gy, 1, true,  false, w, s, nullptr);
    // question encoder: alternating self (mask j<=i) / cross-value (mask j<i, FFN)
    run_block(gx, gx, 2, true,  false, w, s, nullptr);
    run_block(gx, gy, 3, false, true,  w, s, nullptr);
    run_block(gx, gx, 4, true,  false, w, s, nullptr);
    run_block(gx, gy, 5, false, true,  w, s, (float*)d_out);
}

// round 2
// speedup vs baseline: 2.1697x; 2.1697x over previous
#include <cuda_runtime.h>
#include <math.h>
#include <stdint.h>

#define Bn   16
#define Ss   512
#define Dd   512
#define Hh   8
#define HSs  2
#define DKk  64
#define DFFf 2048
#define NGATE 6   // H - HS

// ---------------- scratch (device globals; no allocation allowed) ----------------
__device__ float g_y[Bn*Ss*Dd];
__device__ float g_x[Bn*Ss*Dd];
__device__ float g_qlin[Bn*Ss*Dd];
__device__ float g_v[Bn*Ss*Dd];
__device__ float g_scores[Bn*Hh*Ss*Ss];     // 134 MB
__device__ float g_ctx[Bn*Ss*Dd];
__device__ float g_tmp[Bn*Ss*Dd];
__device__ float g_ffn[Bn*Ss*DFFf];
__device__ float g_dyn[Bn*Ss*NGATE];
__device__ float g_rmask[Bn*Hh];

// ---------------- TF32 helpers ----------------
__device__ __forceinline__ float to_tf32(float x) {
    uint32_t u;
    asm("cvt.rna.tf32.f32 %0, %1;" : "=r"(u) : "f"(x));
    return __uint_as_float(u);
}

__device__ __forceinline__ void mma_tf32(float c[4], uint32_t a0, uint32_t a1,
                                         uint32_t a2, uint32_t a3,
                                         uint32_t b0, uint32_t b1) {
    asm volatile(
        "mma.sync.aligned.m16n8k8.row.col.f32.tf32.tf32.f32 "
        "{%0,%1,%2,%3}, {%4,%5,%6,%7}, {%8,%9}, {%0,%1,%2,%3};"
        : "+f"(c[0]), "+f"(c[1]), "+f"(c[2]), "+f"(c[3])
        : "r"(a0), "r"(a1), "r"(a2), "r"(a3), "r"(b0), "r"(b1));
}

// ---------------- TF32 tensor-core batched GEMM ----------------
// C[z] = epi( alpha * A[z] @ (B[z] or B[z]^T) ), per-z offsets split into
// (batch, head):  off = (z/nH)*s?b + (z%nH)*s?h
// Tiles: BM=128 x BN x BK=32.  8 warps: 2 (M) x 4 (N), warp tile 64 x (BN/4).
template<int BN, bool TRANSB>
__global__ void __launch_bounds__(256) mma_gemm_kernel(
    const float* __restrict__ A, const float* __restrict__ Bm,
    const float* __restrict__ bias, float* __restrict__ C,
    int M, int N, int K, int lda, int ldb, int ldc,
    long long sAb, long long sAh, long long sBb, long long sBh,
    long long sCb, long long sCh, int nH,
    float alpha, const float* __restrict__ scaleZ, int relu)
{
    constexpr int BM = 128, BK = 32;
    constexpr int WN = BN / 4;       // warp N extent
    constexpr int NT = WN / 8;       // n-tiles per warp (4 or 2)
    constexpr int LDA_S = BK + 4;    // 36: frag bank = (4g+t)%32 distinct
    constexpr int LDB_S = BN + 8;    // 136/72: frag bank = (8t+g)%32 distinct
    constexpr int A_F4 = (BM * BK) / (256 * 4);   // 4
    constexpr int B_F4 = (BK * BN) / (256 * 4);   // 4 or 2

    int z = blockIdx.z;
    int zb = z / nH, zh = z % nH;
    A  += zb * sAb + (long long)zh * sAh;
    Bm += zb * sBb + (long long)zh * sBh;
    C  += zb * sCb + (long long)zh * sCh;

    __shared__ __align__(16) float As[BM * LDA_S];
    __shared__ __align__(16) float Bs[BK * LDB_S];

    const int tid = threadIdx.x;
    const int warpId = tid >> 5;
    const int lane = tid & 31;
    const int grp = lane >> 2;        // 0..7
    const int tig = lane & 3;         // 0..3
    const int warpM = warpId & 1;     // 0..1
    const int warpN = warpId >> 1;    // 0..3
    const int row0 = blockIdx.y * BM;
    const int col0 = blockIdx.x * BN;

    float4 aReg[A_F4];
    float4 bReg[B_F4];

    auto loadA = [&](int k0) {
        #pragma unroll
        for (int i = 0; i < A_F4; i++) {
            int f4 = tid + i * 256;
            int r = f4 >> 3, kc = (f4 & 7) * 4;
            aReg[i] = *(const float4*)&A[(long long)(row0 + r) * lda + k0 + kc];
        }
    };
    auto storeA = [&]() {
        #pragma unroll
        for (int i = 0; i < A_F4; i++) {
            int f4 = tid + i * 256;
            int r = f4 >> 3, kc = (f4 & 7) * 4;
            float4 v = aReg[i];
            v.x = to_tf32(v.x); v.y = to_tf32(v.y);
            v.z = to_tf32(v.z); v.w = to_tf32(v.w);
            *(float4*)&As[r * LDA_S + kc] = v;
        }
    };
    auto loadB = [&](int k0) {
        #pragma unroll
        for (int i = 0; i < B_F4; i++) {
            int f4 = tid + i * 256;
            if (TRANSB) {
                int n = f4 >> 3, k4 = (f4 & 7) * 4;
                bReg[i] = *(const float4*)&Bm[(long long)(col0 + n) * ldb + k0 + k4];
            } else {
                int kr = f4 / (BN / 4), nc = (f4 % (BN / 4)) * 4;
                bReg[i] = *(const float4*)&Bm[(long long)(k0 + kr) * ldb + col0 + nc];
            }
        }
    };
    auto storeB = [&]() {
        #pragma unroll
        for (int i = 0; i < B_F4; i++) {
            int f4 = tid + i * 256;
            float4 v = bReg[i];
            v.x = to_tf32(v.x); v.y = to_tf32(v.y);
            v.z = to_tf32(v.z); v.w = to_tf32(v.w);
            if (TRANSB) {
                int n = f4 >> 3, k4 = (f4 & 7) * 4;
                Bs[(k4 + 0) * LDB_S + n] = v.x;
                Bs[(k4 + 1) * LDB_S + n] = v.y;
                Bs[(k4 + 2) * LDB_S + n] = v.z;
                Bs[(k4 + 3) * LDB_S + n] = v.w;
            } else {
                int kr = f4 / (BN / 4), nc = (f4 % (BN / 4)) * 4;
                *(float4*)&Bs[kr * LDB_S + nc] = v;
            }
        }
    };

    float acc[4][NT][4];
    #pragma unroll
    for (int mt = 0; mt < 4; mt++)
        #pragma unroll
        for (int nt = 0; nt < NT; nt++)
            #pragma unroll
            for (int q = 0; q < 4; q++) acc[mt][nt][q] = 0.f;

    const uint32_t* Asu = reinterpret_cast<const uint32_t*>(As);
    const uint32_t* Bsu = reinterpret_cast<const uint32_t*>(Bs);

    const int KT = K / BK;
    loadA(0); loadB(0);
    storeA(); storeB();
    __syncthreads();

    for (int kt = 0; kt < KT; kt++) {
        if (kt + 1 < KT) { loadA((kt + 1) * BK); loadB((kt + 1) * BK); }

        #pragma unroll
        for (int kk = 0; kk < BK; kk += 8) {
            uint32_t af[4][4];
            #pragma unroll
            for (int mt = 0; mt < 4; mt++) {
                int base = (warpM * 64 + mt * 16 + grp) * LDA_S + kk + tig;
                af[mt][0] = Asu[base];
                af[mt][1] = Asu[base + 8 * LDA_S];
                af[mt][2] = Asu[base + 4];
                af[mt][3] = Asu[base + 8 * LDA_S + 4];
            }
            uint32_t bf[NT][2];
            #pragma unroll
            for (int nt = 0; nt < NT; nt++) {
                int base = (kk + tig) * LDB_S + warpN * WN + nt * 8 + grp;
                bf[nt][0] = Bsu[base];
                bf[nt][1] = Bsu[base + 4 * LDB_S];
            }
            #pragma unroll
            for (int mt = 0; mt < 4; mt++)
                #pragma unroll
                for (int nt = 0; nt < NT; nt++)
                    mma_tf32(acc[mt][nt], af[mt][0], af[mt][1], af[mt][2], af[mt][3],
                             bf[nt][0], bf[nt][1]);
        }
        __syncthreads();
        if (kt + 1 < KT) { storeA(); storeB(); __syncthreads(); }
    }

    // ---------------- epilogue ----------------
    float sc = alpha;
    if (scaleZ) sc *= scaleZ[z];
    #pragma unroll
    for (int mt = 0; mt < 4; mt++) {
        #pragma unroll
        for (int nt = 0; nt < NT; nt++) {
            int r0 = row0 + warpM * 64 + mt * 16 + grp;
            int cc = col0 + warpN * WN + nt * 8 + tig * 2;
            float b0 = 0.f, b1 = 0.f;
            if (bias) { b0 = bias[cc]; b1 = bias[cc + 1]; }
            float v0 = acc[mt][nt][0] * sc + b0;
            float v1 = acc[mt][nt][1] * sc + b1;
            float v2 = acc[mt][nt][2] * sc + b0;
            float v3 = acc[mt][nt][3] * sc + b1;
            if (relu) {
                v0 = fmaxf(v0, 0.f); v1 = fmaxf(v1, 0.f);
                v2 = fmaxf(v2, 0.f); v3 = fmaxf(v3, 0.f);
            }
            *(float2*)&C[(long long)r0 * ldc + cc]       = make_float2(v0, v1);
            *(float2*)&C[(long long)(r0 + 8) * ldc + cc] = make_float2(v2, v3);
        }
    }
}

// ---------------- mask + softmax over score rows ----------------
__global__ void softmax_kernel(float* __restrict__ scores, int mask_flag)
{
    long long row = blockIdx.x;
    int i = (int)(row % Ss);
    float* p = scores + row * Ss;
    int tid = threadIdx.x;

    if (i == 0) {   // pad_zero: row forced to 0 before softmax -> uniform
        const float u = 1.0f / Ss;
        for (int j = tid; j < Ss; j += 128) p[j] = u;
        return;
    }
    int limit = mask_flag ? (i + 1) : i;

    __shared__ float red[4];
    float m = -1e30f;
    for (int j = tid; j < limit; j += 128) m = fmaxf(m, p[j]);
    #pragma unroll
    for (int o = 16; o; o >>= 1) m = fmaxf(m, __shfl_xor_sync(0xffffffffu, m, o));
    if ((tid & 31) == 0) red[tid >> 5] = m;
    __syncthreads();
    m = fmaxf(fmaxf(red[0], red[1]), fmaxf(red[2], red[3]));
    __syncthreads();

    float s = 0.f;
    for (int j = tid; j < limit; j += 128) {
        float e = expf(p[j] - m);
        p[j] = e;
        s += e;
    }
    #pragma unroll
    for (int o = 16; o; o >>= 1) s += __shfl_xor_sync(0xffffffffu, s, o);
    if ((tid & 31) == 0) red[tid >> 5] = s;
    __syncthreads();
    s = red[0] + red[1] + red[2] + red[3];
    float inv = 1.0f / s;
    for (int j = tid; j < limit; j += 128) p[j] *= inv;
    for (int j = limit + tid; j < Ss; j += 128) p[j] = 0.f;
}

// ---------------- residual + LayerNorm ----------------
__global__ void add_ln_kernel(const float* __restrict__ resid, const float* __restrict__ delta,
                              const float* __restrict__ g, const float* __restrict__ b,
                              float* __restrict__ out)
{
    long long base = (long long)blockIdx.x * Dd;
    int tid = threadIdx.x;
    float v0 = resid[base + tid]       + delta[base + tid];
    float v1 = resid[base + tid + 256] + delta[base + tid + 256];
    float s  = v0 + v1;
    float sq = v0 * v0 + v1 * v1;

    __shared__ float rs[8], rq[8];
    #pragma unroll
    for (int o = 16; o; o >>= 1) {
        s  += __shfl_xor_sync(0xffffffffu, s,  o);
        sq += __shfl_xor_sync(0xffffffffu, sq, o);
    }
    if ((tid & 31) == 0) { rs[tid >> 5] = s; rq[tid >> 5] = sq; }
    __syncthreads();
    s = 0.f; sq = 0.f;
    #pragma unroll
    for (int w2 = 0; w2 < 8; w2++) { s += rs[w2]; sq += rq[w2]; }

    float mu   = s * (1.0f / Dd);
    float var  = sq * (1.0f / Dd) - mu * mu;
    float rstd = rsqrtf(var + 1e-5f);
    out[base + tid]       = g[tid]       * ((v0 - mu) * rstd) + b[tid];
    out[base + tid + 256] = g[tid + 256] * ((v1 - mu) * rstd) + b[tid + 256];
}

// ---------------- head-routing gate: one warp per token ----------------
__global__ void gating_kernel(const float* __restrict__ qlin, const float* __restrict__ wg,
                              float* __restrict__ dyn)
{
    int gw   = (int)((blockIdx.x * blockDim.x + threadIdx.x) >> 5);
    int lane = threadIdx.x & 31;
    if (gw >= Bn * Ss) return;
    const float* q = qlin + (long long)gw * Dd;

    float acc[NGATE];
    #pragma unroll
    for (int g2 = 0; g2 < NGATE; g2++) acc[g2] = 0.f;
    for (int d = lane; d < Dd; d += 32) {
        float qv = q[d];
        const float* w = wg + d * NGATE;
        #pragma unroll
        for (int g2 = 0; g2 < NGATE; g2++) acc[g2] += qv * w[g2];
    }
    #pragma unroll
    for (int g2 = 0; g2 < NGATE; g2++)
        #pragma unroll
        for (int o = 16; o; o >>= 1) acc[g2] += __shfl_xor_sync(0xffffffffu, acc[g2], o);

    if (lane == 0) {
        int i1 = 0;
        #pragma unroll
        for (int g2 = 1; g2 < NGATE; g2++) if (acc[g2] > acc[i1]) i1 = g2;
        int i2 = (i1 == 0) ? 1 : 0;
        #pragma unroll
        for (int g2 = 0; g2 < NGATE; g2++)
            if (g2 != i1 && acc[g2] > acc[i2]) i2 = g2;

        float mx = acc[i1], sum = 0.f, e[NGATE];
        #pragma unroll
        for (int g2 = 0; g2 < NGATE; g2++) { e[g2] = expf(acc[g2] - mx); sum += e[g2]; }
        float inv = 1.0f / sum;
        #pragma unroll
        for (int g2 = 0; g2 < NGATE; g2++)
            dyn[(long long)gw * NGATE + g2] = (g2 == i1 || g2 == i2) ? e[g2] * inv : 0.f;
    }
}

// ---------------- rmask[b,h] ----------------
__global__ void rmask_kernel(const float* __restrict__ dyn, float* __restrict__ rmask)
{
    int z = blockIdx.x;             // B*H
    int b = z / Hh, h = z % Hh;
    int tid = threadIdx.x;          // 256
    if (h < HSs) { if (tid == 0) rmask[z] = 1.f; return; }
    int g = h - HSs;
    float v = dyn[((long long)(b * Ss + tid))       * NGATE + g]
            + dyn[((long long)(b * Ss + tid + 256)) * NGATE + g];
    __shared__ float rs[8];
    #pragma unroll
    for (int o = 16; o; o >>= 1) v += __shfl_xor_sync(0xffffffffu, v, o);
    if ((tid & 31) == 0) rs[tid >> 5] = v;
    __syncthreads();
    if (tid == 0) {
        float t = 0.f;
        #pragma unroll
        for (int w2 = 0; w2 < 8; w2++) t += rs[w2];
        rmask[z] = t * (1.0f / Ss);
    }
}

// ---------------- host orchestration ----------------
struct Wts {
    const float *wq, *bq, *wv, *bv, *wo, *bo, *wg;
    const float *ln1g, *ln1b, *fw1, *fb1, *fw2, *fb2, *ln2g, *ln2b;
};
struct Scr {
    float *qlin, *v, *scores, *ctx, *tmp, *ffn, *dyn, *rmask;
};

// mode: 0 = BN128 notrans, 1 = BN128 trans, 2 = BN64 notrans
static void gemm(const float* A, const float* Bm, const float* bias, float* C,
                 int M, int N, int K, int lda, int ldb, int ldc,
                 long long sAb, long long sAh, long long sBb, long long sBh,
                 long long sCb, long long sCh, int nH, int batch,
                 float alpha, const float* scaleZ, int mode, int relu)
{
    dim3 blk(256);
    if (mode == 2) {
        dim3 grid(N / 64, M / 128, batch);
        mma_gemm_kernel<64, false><<<grid, blk>>>(A, Bm, bias, C, M, N, K, lda, ldb, ldc,
                                                  sAb, sAh, sBb, sBh, sCb, sCh, nH, alpha, scaleZ, relu);
    } else {
        dim3 grid(N / 128, M / 128, batch);
        if (mode == 1)
            mma_gemm_kernel<128, true><<<grid, blk>>>(A, Bm, bias, C, M, N, K, lda, ldb, ldc,
                                                      sAb, sAh, sBb, sBh, sCb, sCh, nH, alpha, scaleZ, relu);
        else
            mma_gemm_kernel<128, false><<<grid, blk>>>(A, Bm, bias, C, M, N, K, lda, ldb, ldc,
                                                       sAb, sAh, sBb, sBh, sCb, sCh, nH, alpha, scaleZ, relu);
    }
}

static void run_block(float* xq, float* xv, int layer, bool mask_flag, bool apply_pos,
                      const Wts& w, const Scr& s, float* finalOut)
{
    const int M = Bn * Ss;
    const long long DD = (long long)Dd * Dd;

    // qlin = xq @ wq[l] + bq[l]
    gemm(xq, w.wq + layer * DD, w.bq + layer * Dd, s.qlin,
         M, Dd, Dd, Dd, Dd, Dd, 0,0,0,0,0,0, 1, 1, 1.f, nullptr, 0, 0);
    // v = xv @ wv[l] + bv[l]
    gemm(xv, w.wv + layer * DD, w.bv + layer * Dd, s.v,
         M, Dd, Dd, Dd, Dd, Dd, 0,0,0,0,0,0, 1, 1, 1.f, nullptr, 0, 0);

    // head routing
    gating_kernel<<<(Bn * Ss * 32 + 255) / 256, 256>>>(s.qlin, w.wg + (long long)layer * Dd * NGATE, s.dyn);
    rmask_kernel<<<Bn * Hh, 256>>>(s.dyn, s.rmask);

    // scores[z] = (Qh @ Qh^T) / 8
    gemm(s.qlin, s.qlin, nullptr, s.scores,
         Ss, Ss, DKk, Dd, Dd, Ss,
         (long long)Ss * Dd, 64, (long long)Ss * Dd, 64,
         (long long)Hh * Ss * Ss, (long long)Ss * Ss,
         Hh, Bn * Hh, 0.125f, nullptr, 1, 0);

    softmax_kernel<<<Bn * Hh * Ss, 128>>>(s.scores, mask_flag ? 1 : 0);

    // ctx = (attn @ Vh) * rmask[z]
    gemm(s.scores, s.v, nullptr, s.ctx,
         Ss, DKk, Ss, Ss, Dd, Dd,
         (long long)Hh * Ss * Ss, (long long)Ss * Ss,
         (long long)Ss * Dd, 64, (long long)Ss * Dd, 64,
         Hh, Bn * Hh, 1.f, s.rmask, 2, 0);

    // tmp = ctx @ wo[l] + bo[l]
    gemm(s.ctx, w.wo + layer * DD, w.bo + layer * Dd, s.tmp,
         M, Dd, Dd, Dd, Dd, Dd, 0,0,0,0,0,0, 1, 1, 1.f, nullptr, 0, 0);

    // x = LN(xq + tmp)
    add_ln_kernel<<<M, 256>>>(xq, s.tmp, w.ln1g + layer * Dd, w.ln1b + layer * Dd, xq);

    if (apply_pos) {
        gemm(xq, w.fw1 + (long long)layer * Dd * DFFf, w.fb1 + layer * DFFf, s.ffn,
             M, DFFf, Dd, Dd, DFFf, DFFf, 0,0,0,0,0,0, 1, 1, 1.f, nullptr, 0, 1);
        gemm(s.ffn, w.fw2 + (long long)layer * DFFf * Dd, w.fb2 + layer * Dd, s.tmp,
             M, Dd, DFFf, DFFf, Dd, Dd, 0,0,0,0,0,0, 1, 1, 1.f, nullptr, 0, 0);
        float* out2 = finalOut ? finalOut : xq;
        add_ln_kernel<<<M, 256>>>(xq, s.tmp, w.ln2g + layer * Dd, w.ln2b + layer * Dd, out2);
    }
}

extern "C" void kernel_launch(void* const* d_in, const int* in_sizes, int n_in,
                              void* d_out, int out_size)
{
    const float* question    = (const float*)d_in[0];
    const float* interaction = (const float*)d_in[1];
    Wts w;
    w.wq   = (const float*)d_in[2];  w.bq   = (const float*)d_in[3];
    w.wv   = (const float*)d_in[4];  w.bv   = (const float*)d_in[5];
    w.wo   = (const float*)d_in[6];  w.bo   = (const float*)d_in[7];
    w.wg   = (const float*)d_in[8];
    w.ln1g = (const float*)d_in[9];  w.ln1b = (const float*)d_in[10];
    w.fw1  = (const float*)d_in[11]; w.fb1  = (const float*)d_in[12];
    w.fw2  = (const float*)d_in[13]; w.fb2  = (const float*)d_in[14];
    w.ln2g = (const float*)d_in[15]; w.ln2b = (const float*)d_in[16];

    float *gx, *gy;
    Scr s;
    cudaGetSymbolAddress((void**)&gx,       g_x);
    cudaGetSymbolAddress((void**)&gy,       g_y);
    cudaGetSymbolAddress((void**)&s.qlin,   g_qlin);
    cudaGetSymbolAddress((void**)&s.v,      g_v);
    cudaGetSymbolAddress((void**)&s.scores, g_scores);
    cudaGetSymbolAddress((void**)&s.ctx,    g_ctx);
    cudaGetSymbolAddress((void**)&s.tmp,    g_tmp);
    cudaGetSymbolAddress((void**)&s.ffn,    g_ffn);
    cudaGetSymbolAddress((void**)&s.dyn,    g_dyn);
    cudaGetSymbolAddress((void**)&s.rmask,  g_rmask);

    size_t bytes = (size_t)Bn * Ss * Dd * sizeof(float);
    cudaMemcpyAsync(gy, interaction, bytes, cudaMemcpyDeviceToDevice);
    cudaMemcpyAsync(gx, question,    bytes, cudaMemcpyDeviceToDevice);

    // knowledge encoder
    run_block(gy, gy, 0, true,  false, w, s, nullptr);
    run_block(gy, gy, 1, true,  false, w, s, nullptr);
    // question encoder
    run_block(gx, gx, 2, true,  false, w, s, nullptr);
    run_block(gx, gy, 3, false, true,  w, s, nullptr);
    run_block(gx, gx, 4, true,  false, w, s, nullptr);
    run_block(gx, gy, 5, false, true,  w, s, (float*)d_out);
}

// round 3
// speedup vs baseline: 2.9163x; 1.3441x over previous
#include <cuda_runtime.h>
#include <math.h>
#include <stdint.h>

#define Bn   16
#define Ss   512
#define Dd   512
#define Hh   8
#define HSs  2
#define DKk  64
#define DFFf 2048
#define NGATE 6   // H - HS

// ---------------- scratch (device globals; no allocation allowed) ----------------
__device__ float g_y[Bn*Ss*Dd];
__device__ float g_x[Bn*Ss*Dd];
__device__ float g_qlin[Bn*Ss*Dd];
__device__ float g_v[Bn*Ss*Dd];
__device__ float g_ctx[Bn*Ss*Dd];
__device__ float g_tmp[Bn*Ss*Dd];
__device__ float g_ffn[Bn*Ss*DFFf];
__device__ float g_dyn[Bn*Ss*NGATE];
__device__ float g_rmask[Bn*Hh];

// ---------------- TF32 helpers ----------------
__device__ __forceinline__ float to_tf32(float x) {
    uint32_t u;
    asm("cvt.rna.tf32.f32 %0, %1;" : "=r"(u) : "f"(x));
    return __uint_as_float(u);
}

__device__ __forceinline__ void mma_tf32(float c[4], uint32_t a0, uint32_t a1,
                                         uint32_t a2, uint32_t a3,
                                         uint32_t b0, uint32_t b1) {
    asm volatile(
        "mma.sync.aligned.m16n8k8.row.col.f32.tf32.tf32.f32 "
        "{%0,%1,%2,%3}, {%4,%5,%6,%7}, {%8,%9}, {%0,%1,%2,%3};"
        : "+f"(c[0]), "+f"(c[1]), "+f"(c[2]), "+f"(c[3])
        : "r"(a0), "r"(a1), "r"(a2), "r"(a3), "r"(b0), "r"(b1));
}

// ---------------- TF32 tensor-core batched GEMM (projections / FFN) ----------------
template<int BN, bool TRANSB>
__global__ void __launch_bounds__(256) mma_gemm_kernel(
    const float* __restrict__ A, const float* __restrict__ Bm,
    const float* __restrict__ bias, float* __restrict__ C,
    int M, int N, int K, int lda, int ldb, int ldc,
    long long sAb, long long sAh, long long sBb, long long sBh,
    long long sCb, long long sCh, int nH,
    float alpha, const float* __restrict__ scaleZ, int relu)
{
    constexpr int BM = 128, BK = 32;
    constexpr int WN = BN / 4;
    constexpr int NT = WN / 8;
    constexpr int LDA_S = BK + 4;
    constexpr int LDB_S = BN + 8;
    constexpr int A_F4 = (BM * BK) / (256 * 4);
    constexpr int B_F4 = (BK * BN) / (256 * 4);

    int z = blockIdx.z;
    int zb = z / nH, zh = z % nH;
    A  += zb * sAb + (long long)zh * sAh;
    Bm += zb * sBb + (long long)zh * sBh;
    C  += zb * sCb + (long long)zh * sCh;

    __shared__ __align__(16) float As[BM * LDA_S];
    __shared__ __align__(16) float Bs[BK * LDB_S];

    const int tid = threadIdx.x;
    const int warpId = tid >> 5;
    const int lane = tid & 31;
    const int grp = lane >> 2;
    const int tig = lane & 3;
    const int warpM = warpId & 1;
    const int warpN = warpId >> 1;
    const int row0 = blockIdx.y * BM;
    const int col0 = blockIdx.x * BN;

    float4 aReg[A_F4];
    float4 bReg[B_F4];

    auto loadA = [&](int k0) {
        #pragma unroll
        for (int i = 0; i < A_F4; i++) {
            int f4 = tid + i * 256;
            int r = f4 >> 3, kc = (f4 & 7) * 4;
            aReg[i] = *(const float4*)&A[(long long)(row0 + r) * lda + k0 + kc];
        }
    };
    auto storeA = [&]() {
        #pragma unroll
        for (int i = 0; i < A_F4; i++) {
            int f4 = tid + i * 256;
            int r = f4 >> 3, kc = (f4 & 7) * 4;
            float4 v = aReg[i];
            v.x = to_tf32(v.x); v.y = to_tf32(v.y);
            v.z = to_tf32(v.z); v.w = to_tf32(v.w);
            *(float4*)&As[r * LDA_S + kc] = v;
        }
    };
    auto loadB = [&](int k0) {
        #pragma unroll
        for (int i = 0; i < B_F4; i++) {
            int f4 = tid + i * 256;
            if (TRANSB) {
                int n = f4 >> 3, k4 = (f4 & 7) * 4;
                bReg[i] = *(const float4*)&Bm[(long long)(col0 + n) * ldb + k0 + k4];
            } else {
                int kr = f4 / (BN / 4), nc = (f4 % (BN / 4)) * 4;
                bReg[i] = *(const float4*)&Bm[(long long)(k0 + kr) * ldb + col0 + nc];
            }
        }
    };
    auto storeB = [&]() {
        #pragma unroll
        for (int i = 0; i < B_F4; i++) {
            int f4 = tid + i * 256;
            float4 v = bReg[i];
            v.x = to_tf32(v.x); v.y = to_tf32(v.y);
            v.z = to_tf32(v.z); v.w = to_tf32(v.w);
            if (TRANSB) {
                int n = f4 >> 3, k4 = (f4 & 7) * 4;
                Bs[(k4 + 0) * LDB_S + n] = v.x;
                Bs[(k4 + 1) * LDB_S + n] = v.y;
                Bs[(k4 + 2) * LDB_S + n] = v.z;
                Bs[(k4 + 3) * LDB_S + n] = v.w;
            } else {
                int kr = f4 / (BN / 4), nc = (f4 % (BN / 4)) * 4;
                *(float4*)&Bs[kr * LDB_S + nc] = v;
            }
        }
    };

    float acc[4][NT][4];
    #pragma unroll
    for (int mt = 0; mt < 4; mt++)
        #pragma unroll
        for (int nt = 0; nt < NT; nt++)
            #pragma unroll
            for (int q = 0; q < 4; q++) acc[mt][nt][q] = 0.f;

    const uint32_t* Asu = reinterpret_cast<const uint32_t*>(As);
    const uint32_t* Bsu = reinterpret_cast<const uint32_t*>(Bs);

    const int KT = K / BK;
    loadA(0); loadB(0);
    storeA(); storeB();
    __syncthreads();

    for (int kt = 0; kt < KT; kt++) {
        if (kt + 1 < KT) { loadA((kt + 1) * BK); loadB((kt + 1) * BK); }

        #pragma unroll
        for (int kk = 0; kk < BK; kk += 8) {
            uint32_t af[4][4];
            #pragma unroll
            for (int mt = 0; mt < 4; mt++) {
                int base = (warpM * 64 + mt * 16 + grp) * LDA_S + kk + tig;
                af[mt][0] = Asu[base];
                af[mt][1] = Asu[base + 8 * LDA_S];
                af[mt][2] = Asu[base + 4];
                af[mt][3] = Asu[base + 8 * LDA_S + 4];
            }
            uint32_t bf[NT][2];
            #pragma unroll
            for (int nt = 0; nt < NT; nt++) {
                int base = (kk + tig) * LDB_S + warpN * WN + nt * 8 + grp;
                bf[nt][0] = Bsu[base];
                bf[nt][1] = Bsu[base + 4 * LDB_S];
            }
            #pragma unroll
            for (int mt = 0; mt < 4; mt++)
                #pragma unroll
                for (int nt = 0; nt < NT; nt++)
                    mma_tf32(acc[mt][nt], af[mt][0], af[mt][1], af[mt][2], af[mt][3],
                             bf[nt][0], bf[nt][1]);
        }
        __syncthreads();
        if (kt + 1 < KT) { storeA(); storeB(); __syncthreads(); }
    }

    float sc = alpha;
    if (scaleZ) sc *= scaleZ[z];
    #pragma unroll
    for (int mt = 0; mt < 4; mt++) {
        #pragma unroll
        for (int nt = 0; nt < NT; nt++) {
            int r0 = row0 + warpM * 64 + mt * 16 + grp;
            int cc = col0 + warpN * WN + nt * 8 + tig * 2;
            float b0 = 0.f, b1 = 0.f;
            if (bias) { b0 = bias[cc]; b1 = bias[cc + 1]; }
            float v0 = acc[mt][nt][0] * sc + b0;
            float v1 = acc[mt][nt][1] * sc + b1;
            float v2 = acc[mt][nt][2] * sc + b0;
            float v3 = acc[mt][nt][3] * sc + b1;
            if (relu) {
                v0 = fmaxf(v0, 0.f); v1 = fmaxf(v1, 0.f);
                v2 = fmaxf(v2, 0.f); v3 = fmaxf(v3, 0.f);
            }
            *(float2*)&C[(long long)r0 * ldc + cc]       = make_float2(v0, v1);
            *(float2*)&C[(long long)(r0 + 8) * ldc + cc] = make_float2(v2, v3);
        }
    }
}

// ---------------- fused flash attention ----------------
// grid (S/64, B*H). Per block: 64 q-rows x full causal key range for one head.
// ctx[b, i, h*64+d] = rmask[b,h] * softmax(mask(QK^T/8))[i,:] @ V   (rows 1..511;
// row 0 written garbage here, overwritten by pad_row_kernel).
// Smem layout (floats): Qs[64*68] | KPs[64*68] (K tile then P tile) | Vs[64*72]
//                       | redm[2*64] | reds[2*64] | m_s[64] | l_s[64]
#define FL_QS   0
#define FL_KP   (64*68)
#define FL_VS   (FL_KP + 64*68)
#define FL_REDM (FL_VS + 64*72)
#define FL_REDS (FL_REDM + 128)
#define FL_M    (FL_REDS + 128)
#define FL_L    (FL_M + 64)
#define FL_TOT  (FL_L + 64)
#define FL_BYTES (FL_TOT * 4)

__global__ void __launch_bounds__(256) flash_attn_kernel(
    const float* __restrict__ qlin, const float* __restrict__ v,
    const float* __restrict__ rmask, float* __restrict__ ctx, int mask_flag)
{
    extern __shared__ float sm[];
    float* Qs  = sm + FL_QS;
    float* KPs = sm + FL_KP;
    float* Vs  = sm + FL_VS;
    float* redm = sm + FL_REDM;
    float* reds = sm + FL_REDS;
    float* m_s  = sm + FL_M;
    float* l_s  = sm + FL_L;

    const int z = blockIdx.y;           // b*H + h
    const int b = z >> 3, h = z & 7;
    const int q0 = blockIdx.x * 64;
    const float* Qg = qlin + (long long)b * Ss * Dd + h * 64;
    const float* Vg = v    + (long long)b * Ss * Dd + h * 64;

    const int tid = threadIdx.x;
    const int warpId = tid >> 5, lane = tid & 31;
    const int grp = lane >> 2, tig = lane & 3;
    const int warpM = warpId >> 1, warpN = warpId & 1;
    const int row_a = warpM * 16 + grp;          // local row (also +8)

    // load Q tile, pre-scaled by 1/8 (exact pow2)
    #pragma unroll
    for (int i = 0; i < 4; i++) {
        int id = tid + i * 256;
        int r = id >> 4, c4 = (id & 15) * 4;
        float4 q4 = *(const float4*)&Qg[(long long)(q0 + r) * Dd + c4];
        q4.x = to_tf32(q4.x * 0.125f); q4.y = to_tf32(q4.y * 0.125f);
        q4.z = to_tf32(q4.z * 0.125f); q4.w = to_tf32(q4.w * 0.125f);
        *(float4*)&Qs[r * 68 + c4] = q4;
    }
    if (tid < 64) { m_s[tid] = -1e30f; l_s[tid] = 0.f; }

    float Oa[4][4];
    #pragma unroll
    for (int nt = 0; nt < 4; nt++)
        #pragma unroll
        for (int q = 0; q < 4; q++) Oa[nt][q] = 0.f;

    const uint32_t* Qu  = reinterpret_cast<const uint32_t*>(Qs);
    const uint32_t* KPu = reinterpret_cast<const uint32_t*>(KPs);
    const uint32_t* Vu  = reinterpret_cast<const uint32_t*>(Vs);

    const int nTiles = blockIdx.x + 1;           // causal: tiles 0..q-tile

    for (int kt = 0; kt < nTiles; kt++) {
        const int k0 = kt * 64;
        // load K (= qlin) and V tiles
        #pragma unroll
        for (int i = 0; i < 4; i++) {
            int id = tid + i * 256;
            int r = id >> 4, c4 = (id & 15) * 4;
            float4 k4 = *(const float4*)&Qg[(long long)(k0 + r) * Dd + c4];
            k4.x = to_tf32(k4.x); k4.y = to_tf32(k4.y);
            k4.z = to_tf32(k4.z); k4.w = to_tf32(k4.w);
            *(float4*)&KPs[r * 68 + c4] = k4;
            float4 v4 = *(const float4*)&Vg[(long long)(k0 + r) * Dd + c4];
            v4.x = to_tf32(v4.x); v4.y = to_tf32(v4.y);
            v4.z = to_tf32(v4.z); v4.w = to_tf32(v4.w);
            *(float4*)&Vs[r * 72 + c4] = v4;
        }
        __syncthreads();

        // S = Q(scaled) @ K^T : warp -> rows [warpM*16,+16), cols [warpN*32,+32)
        float scf[4][4];
        #pragma unroll
        for (int nt = 0; nt < 4; nt++)
            #pragma unroll
            for (int q = 0; q < 4; q++) scf[nt][q] = 0.f;

        #pragma unroll
        for (int kk = 0; kk < 64; kk += 8) {
            uint32_t a0 = Qu[(row_a)     * 68 + kk + tig];
            uint32_t a1 = Qu[(row_a + 8) * 68 + kk + tig];
            uint32_t a2 = Qu[(row_a)     * 68 + kk + tig + 4];
            uint32_t a3 = Qu[(row_a + 8) * 68 + kk + tig + 4];
            #pragma unroll
            for (int nt = 0; nt < 4; nt++) {
                int nc = warpN * 32 + nt * 8 + grp;
                uint32_t b0 = KPu[nc * 68 + kk + tig];
                uint32_t b1 = KPu[nc * 68 + kk + tig + 4];
                mma_tf32(scf[nt], a0, a1, a2, a3, b0, b1);
            }
        }

        // mask only needed on diagonal tile
        if (kt == nTiles - 1) {
            int iA = q0 + row_a, iB = iA + 8;
            int limA = iA + (mask_flag ? 1 : 0);
            int limB = iB + (mask_flag ? 1 : 0);
            #pragma unroll
            for (int nt = 0; nt < 4; nt++) {
                int j0 = k0 + warpN * 32 + nt * 8 + tig * 2;
                if (j0     >= limA) scf[nt][0] = -1e30f;
                if (j0 + 1 >= limA) scf[nt][1] = -1e30f;
                if (j0     >= limB) scf[nt][2] = -1e30f;
                if (j0 + 1 >= limB) scf[nt][3] = -1e30f;
            }
        }

        float mA_old = m_s[row_a], mB_old = m_s[row_a + 8];

        // row max over this tile
        float tmA = -1e30f, tmB = -1e30f;
        #pragma unroll
        for (int nt = 0; nt < 4; nt++) {
            tmA = fmaxf(tmA, fmaxf(scf[nt][0], scf[nt][1]));
            tmB = fmaxf(tmB, fmaxf(scf[nt][2], scf[nt][3]));
        }
        tmA = fmaxf(tmA, __shfl_xor_sync(0xffffffffu, tmA, 1));
        tmA = fmaxf(tmA, __shfl_xor_sync(0xffffffffu, tmA, 2));
        tmB = fmaxf(tmB, __shfl_xor_sync(0xffffffffu, tmB, 1));
        tmB = fmaxf(tmB, __shfl_xor_sync(0xffffffffu, tmB, 2));
        if (tig == 0) {
            redm[warpN * 64 + row_a]     = tmA;
            redm[warpN * 64 + row_a + 8] = tmB;
        }
        __syncthreads();   // also: all QK reads of KPs done -> safe to write P

        float mA = fmaxf(mA_old, fmaxf(redm[row_a],     redm[64 + row_a]));
        float mB = fmaxf(mB_old, fmaxf(redm[row_a + 8], redm[64 + row_a + 8]));
        float alA = __expf(mA_old - mA);
        float alB = __expf(mB_old - mB);

        // P = exp(S - m), write into KPs; partial row sums; rescale O
        float psA = 0.f, psB = 0.f;
        #pragma unroll
        for (int nt = 0; nt < 4; nt++) {
            float p0 = __expf(scf[nt][0] - mA);
            float p1 = __expf(scf[nt][1] - mA);
            float p2 = __expf(scf[nt][2] - mB);
            float p3 = __expf(scf[nt][3] - mB);
            psA += p0 + p1; psB += p2 + p3;
            int nc = warpN * 32 + nt * 8 + tig * 2;
            KPs[row_a * 68 + nc]           = to_tf32(p0);
            KPs[row_a * 68 + nc + 1]       = to_tf32(p1);
            KPs[(row_a + 8) * 68 + nc]     = to_tf32(p2);
            KPs[(row_a + 8) * 68 + nc + 1] = to_tf32(p3);
            Oa[nt][0] *= alA; Oa[nt][1] *= alA;
            Oa[nt][2] *= alB; Oa[nt][3] *= alB;
        }
        psA += __shfl_xor_sync(0xffffffffu, psA, 1);
        psA += __shfl_xor_sync(0xffffffffu, psA, 2);
        psB += __shfl_xor_sync(0xffffffffu, psB, 1);
        psB += __shfl_xor_sync(0xffffffffu, psB, 2);
        if (tig == 0) {
            reds[warpN * 64 + row_a]     = psA;
            reds[warpN * 64 + row_a + 8] = psB;
        }
        if (warpN == 0 && tig == 0) {
            m_s[row_a]     = mA;
            m_s[row_a + 8] = mB;
        }
        __syncthreads();   // P + reds visible

        if (warpN == 0 && tig == 0) {
            l_s[row_a]     = alA * l_s[row_a]     + reds[row_a]     + reds[64 + row_a];
            l_s[row_a + 8] = alB * l_s[row_a + 8] + reds[row_a + 8] + reds[64 + row_a + 8];
        }

        // O += P @ V : A = P[16x64] from KPs, B = V[64x32] from Vs
        #pragma unroll
        for (int kk = 0; kk < 64; kk += 8) {
            uint32_t a0 = KPu[(row_a)     * 68 + kk + tig];
            uint32_t a1 = KPu[(row_a + 8) * 68 + kk + tig];
            uint32_t a2 = KPu[(row_a)     * 68 + kk + tig + 4];
            uint32_t a3 = KPu[(row_a + 8) * 68 + kk + tig + 4];
            #pragma unroll
            for (int nt = 0; nt < 4; nt++) {
                int nc = warpN * 32 + nt * 8 + grp;
                uint32_t b0 = Vu[(kk + tig)     * 72 + nc];
                uint32_t b1 = Vu[(kk + tig + 4) * 72 + nc];
                mma_tf32(Oa[nt], a0, a1, a2, a3, b0, b1);
            }
        }
        __syncthreads();   // protect KPs/Vs before next tile load; l_s final
    }

    // epilogue: normalize, apply rmask, write ctx in (B,S,D) layout
    float rm = rmask[z];
    float invA = rm / l_s[row_a];
    float invB = rm / l_s[row_a + 8];
    #pragma unroll
    for (int nt = 0; nt < 4; nt++) {
        int col = h * 64 + warpN * 32 + nt * 8 + tig * 2;
        long long oA = ((long long)b * Ss + q0 + row_a) * Dd + col;
        long long oB = oA + 8LL * Dd;
        *(float2*)&ctx[oA] = make_float2(Oa[nt][0] * invA, Oa[nt][1] * invA);
        *(float2*)&ctx[oB] = make_float2(Oa[nt][2] * invB, Oa[nt][3] * invB);
    }
}

// ---------------- pad row 0: ctx[b,0,h*64+d] = rmask * mean_j V[b,j,h*64+d] ----------------
__global__ void pad_row_kernel(const float* __restrict__ v, const float* __restrict__ rmask,
                               float* __restrict__ ctx)
{
    int z = blockIdx.x;                 // B*H
    int b = z >> 3, h = z & 7;
    int tid = threadIdx.x;              // 256: (chunk 0..3) x (d 0..63)
    int d = tid & 63, chunk = tid >> 6;
    const float* Vg = v + (long long)b * Ss * Dd + h * 64 + d;
    float s = 0.f;
    for (int j = chunk * 128; j < (chunk + 1) * 128; j++)
        s += Vg[(long long)j * Dd];
    __shared__ float red[256];
    red[tid] = s;
    __syncthreads();
    if (tid < 64) {
        float t = red[tid] + red[tid + 64] + red[tid + 128] + red[tid + 192];
        ctx[(long long)b * Ss * Dd + h * 64 + tid] = t * (1.0f / Ss) * rmask[z];
    }
}

// ---------------- residual + LayerNorm ----------------
__global__ void add_ln_kernel(const float* __restrict__ resid, const float* __restrict__ delta,
                              const float* __restrict__ g, const float* __restrict__ b,
                              float* __restrict__ out)
{
    long long base = (long long)blockIdx.x * Dd;
    int tid = threadIdx.x;
    float v0 = resid[base + tid]       + delta[base + tid];
    float v1 = resid[base + tid + 256] + delta[base + tid + 256];
    float s  = v0 + v1;
    float sq = v0 * v0 + v1 * v1;

    __shared__ float rs[8], rq[8];
    #pragma unroll
    for (int o = 16; o; o >>= 1) {
        s  += __shfl_xor_sync(0xffffffffu, s,  o);
        sq += __shfl_xor_sync(0xffffffffu, sq, o);
    }
    if ((tid & 31) == 0) { rs[tid >> 5] = s; rq[tid >> 5] = sq; }
    __syncthreads();
    s = 0.f; sq = 0.f;
    #pragma unroll
    for (int w2 = 0; w2 < 8; w2++) { s += rs[w2]; sq += rq[w2]; }

    float mu   = s * (1.0f / Dd);
    float var  = sq * (1.0f / Dd) - mu * mu;
    float rstd = rsqrtf(var + 1e-5f);
    out[base + tid]       = g[tid]       * ((v0 - mu) * rstd) + b[tid];
    out[base + tid + 256] = g[tid + 256] * ((v1 - mu) * rstd) + b[tid + 256];
}

// ---------------- head-routing gate: one warp per token ----------------
__global__ void gating_kernel(const float* __restrict__ qlin, const float* __restrict__ wg,
                              float* __restrict__ dyn)
{
    int gw   = (int)((blockIdx.x * blockDim.x + threadIdx.x) >> 5);
    int lane = threadIdx.x & 31;
    if (gw >= Bn * Ss) return;
    const float* q = qlin + (long long)gw * Dd;

    float acc[NGATE];
    #pragma unroll
    for (int g2 = 0; g2 < NGATE; g2++) acc[g2] = 0.f;
    for (int d = lane; d < Dd; d += 32) {
        float qv = q[d];
        const float* w = wg + d * NGATE;
        #pragma unroll
        for (int g2 = 0; g2 < NGATE; g2++) acc[g2] += qv * w[g2];
    }
    #pragma unroll
    for (int g2 = 0; g2 < NGATE; g2++)
        #pragma unroll
        for (int o = 16; o; o >>= 1) acc[g2] += __shfl_xor_sync(0xffffffffu, acc[g2], o);

    if (lane == 0) {
        int i1 = 0;
        #pragma unroll
        for (int g2 = 1; g2 < NGATE; g2++) if (acc[g2] > acc[i1]) i1 = g2;
        int i2 = (i1 == 0) ? 1 : 0;
        #pragma unroll
        for (int g2 = 0; g2 < NGATE; g2++)
            if (g2 != i1 && acc[g2] > acc[i2]) i2 = g2;

        float mx = acc[i1], sum = 0.f, e[NGATE];
        #pragma unroll
        for (int g2 = 0; g2 < NGATE; g2++) { e[g2] = expf(acc[g2] - mx); sum += e[g2]; }
        float inv = 1.0f / sum;
        #pragma unroll
        for (int g2 = 0; g2 < NGATE; g2++)
            dyn[(long long)gw * NGATE + g2] = (g2 == i1 || g2 == i2) ? e[g2] * inv : 0.f;
    }
}

// ---------------- rmask[b,h] ----------------
__global__ void rmask_kernel(const float* __restrict__ dyn, float* __restrict__ rmask)
{
    int z = blockIdx.x;             // B*H
    int b = z / Hh, h = z % Hh;
    int tid = threadIdx.x;          // 256
    if (h < HSs) { if (tid == 0) rmask[z] = 1.f; return; }
    int g = h - HSs;
    float v = dyn[((long long)(b * Ss + tid))       * NGATE + g]
            + dyn[((long long)(b * Ss + tid + 256)) * NGATE + g];
    __shared__ float rs[8];
    #pragma unroll
    for (int o = 16; o; o >>= 1) v += __shfl_xor_sync(0xffffffffu, v, o);
    if ((tid & 31) == 0) rs[tid >> 5] = v;
    __syncthreads();
    if (tid == 0) {
        float t = 0.f;
        #pragma unroll
        for (int w2 = 0; w2 < 8; w2++) t += rs[w2];
        rmask[z] = t * (1.0f / Ss);
    }
}

// ---------------- host orchestration ----------------
struct Wts {
    const float *wq, *bq, *wv, *bv, *wo, *bo, *wg;
    const float *ln1g, *ln1b, *fw1, *fb1, *fw2, *fb2, *ln2g, *ln2b;
};
struct Scr {
    float *qlin, *v, *ctx, *tmp, *ffn, *dyn, *rmask;
};

static void gemm_dense(const float* A, const float* Bm, const float* bias, float* C,
                       int M, int N, int K, float alpha, int relu)
{
    dim3 blk(256), grid(N / 128, M / 128, 1);
    mma_gemm_kernel<128, false><<<grid, blk>>>(A, Bm, bias, C, M, N, K, K, N, N,
                                               0, 0, 0, 0, 0, 0, 1, alpha, nullptr, relu);
}

static void run_block(float* xq, float* xv, int layer, bool mask_flag, bool apply_pos,
                      const Wts& w, const Scr& s, float* finalOut)
{
    const int M = Bn * Ss;
    const long long DD = (long long)Dd * Dd;

    gemm_dense(xq, w.wq + layer * DD, w.bq + layer * Dd, s.qlin, M, Dd, Dd, 1.f, 0);
    gemm_dense(xv, w.wv + layer * DD, w.bv + layer * Dd, s.v,    M, Dd, Dd, 1.f, 0);

    gating_kernel<<<(Bn * Ss * 32 + 255) / 256, 256>>>(s.qlin, w.wg + (long long)layer * Dd * NGATE, s.dyn);
    rmask_kernel<<<Bn * Hh, 256>>>(s.dyn, s.rmask);

    // fused attention (scores never materialized)
    flash_attn_kernel<<<dim3(Ss / 64, Bn * Hh), 256, FL_BYTES>>>(
        s.qlin, s.v, s.rmask, s.ctx, mask_flag ? 1 : 0);
    pad_row_kernel<<<Bn * Hh, 256>>>(s.v, s.rmask, s.ctx);

    gemm_dense(s.ctx, w.wo + layer * DD, w.bo + layer * Dd, s.tmp, M, Dd, Dd, 1.f, 0);

    add_ln_kernel<<<M, 256>>>(xq, s.tmp, w.ln1g + layer * Dd, w.ln1b + layer * Dd, xq);

    if (apply_pos) {
        gemm_dense(xq, w.fw1 + (long long)layer * Dd * DFFf, w.fb1 + layer * DFFf, s.ffn,
                   M, DFFf, Dd, 1.f, 1);
        gemm_dense(s.ffn, w.fw2 + (long long)layer * DFFf * Dd, w.fb2 + layer * Dd, s.tmp,
                   M, Dd, DFFf, 1.f, 0);
        float* out2 = finalOut ? finalOut : xq;
        add_ln_kernel<<<M, 256>>>(xq, s.tmp, w.ln2g + layer * Dd, w.ln2b + layer * Dd, out2);
    }
}

extern "C" void kernel_launch(void* const* d_in, const int* in_sizes, int n_in,
                              void* d_out, int out_size)
{
    const float* question    = (const float*)d_in[0];
    const float* interaction = (const float*)d_in[1];
    Wts w;
    w.wq   = (const float*)d_in[2];  w.bq   = (const float*)d_in[3];
    w.wv   = (const float*)d_in[4];  w.bv   = (const float*)d_in[5];
    w.wo   = (const float*)d_in[6];  w.bo   = (const float*)d_in[7];
    w.wg   = (const float*)d_in[8];
    w.ln1g = (const float*)d_in[9];  w.ln1b = (const float*)d_in[10];
    w.fw1  = (const float*)d_in[11]; w.fb1  = (const float*)d_in[12];
    w.fw2  = (const float*)d_in[13]; w.fb2  = (const float*)d_in[14];
    w.ln2g = (const float*)d_in[15]; w.ln2b = (const float*)d_in[16];

    cudaFuncSetAttribute(flash_attn_kernel,
                         cudaFuncAttributeMaxDynamicSharedMemorySize, FL_BYTES);

    float *gx, *gy;
    Scr s;
    cudaGetSymbolAddress((void**)&gx,      g_x);
    cudaGetSymbolAddress((void**)&gy,      g_y);
    cudaGetSymbolAddress((void**)&s.qlin,  g_qlin);
    cudaGetSymbolAddress((void**)&s.v,     g_v);
    cudaGetSymbolAddress((void**)&s.ctx,   g_ctx);
    cudaGetSymbolAddress((void**)&s.tmp,   g_tmp);
    cudaGetSymbolAddress((void**)&s.ffn,   g_ffn);
    cudaGetSymbolAddress((void**)&s.dyn,   g_dyn);
    cudaGetSymbolAddress((void**)&s.rmask, g_rmask);

    size_t bytes = (size_t)Bn * Ss * Dd * sizeof(float);
    cudaMemcpyAsync(gy, interaction, bytes, cudaMemcpyDeviceToDevice);
    cudaMemcpyAsync(gx, question,    bytes, cudaMemcpyDeviceToDevice);

    // knowledge encoder
    run_block(gy, gy, 0, true,  false, w, s, nullptr);
    run_block(gy, gy, 1, true,  false, w, s, nullptr);
    // question encoder
    run_block(gx, gx, 2, true,  false, w, s, nullptr);
    run_block(gx, gy, 3, false, true,  w, s, nullptr);
    run_block(gx, gx, 4, true,  false, w, s, nullptr);
    run_block(gx, gy, 5, false, true,  w, s, (float*)d_out);
}